// round 1
// baseline (speedup 1.0000x reference)
#include <cuda_runtime.h>

// Problem shape (fixed by the dataset)
#define BB 4
#define NN 4096
#define DD 64
#define TM 64
#define TN 64
#define PITCH 68   // smem row pitch in floats: keeps 16B alignment, reduces bank conflicts

#define NEG_INF (-1e9f)
#define ADJ_SCALE 10.0f

// Allocation-free scratch: reciprocal norms 1/||x_row||
__device__ float g_rnorm[BB * NN];

// ---------------------------------------------------------------------------
// Kernel 1: per-row reciprocal norms. One warp per row (D=64 -> 2 floats/lane)
// ---------------------------------------------------------------------------
__global__ void norm_kernel(const float* __restrict__ x) {
    int row  = blockIdx.x * 8 + (threadIdx.x >> 5);
    int lane = threadIdx.x & 31;
    const float* xr = x + (size_t)row * DD;
    float v0 = xr[lane];
    float v1 = xr[lane + 32];
    float s = v0 * v0 + v1 * v1;
    #pragma unroll
    for (int off = 16; off > 0; off >>= 1)
        s += __shfl_xor_sync(0xffffffffu, s, off);
    if (lane == 0)
        g_rnorm[row] = 1.0f / sqrtf(s);
}

// ---------------------------------------------------------------------------
// Kernel 2: fused flash-style attention.
//   grid = (N/TM, B), block = 256 threads as a 16x16 register-tile grid.
//   Each thread owns a 4x4 tile of S / P and a 4x4 tile of the output.
// smem layout (floats): Qt[64][PITCH] | Kt[64][PITCH] | V[64][64] | Pt[64][PITCH]
// ---------------------------------------------------------------------------
#define SMEM_FLOATS (2 * 64 * PITCH + 64 * 64 + 64 * PITCH)
#define SMEM_BYTES  (SMEM_FLOATS * 4)

__global__ __launch_bounds__(256, 2)
void attn_kernel(const float* __restrict__ x,
                 const float* __restrict__ adj,
                 const float* __restrict__ betap,
                 float* __restrict__ out) {
    extern __shared__ float sm[];
    float* sQt = sm;                          // [64][PITCH] dim-major Q^T
    float* sKt = sm + 64 * PITCH;             // [64][PITCH] dim-major K^T
    float* sV  = sm + 2 * 64 * PITCH;         // [64][64]    key-major V (=K tile)
    float* sPt = sm + 2 * 64 * PITCH + 64 * 64; // [64][PITCH] key-major P^T

    const int tid = threadIdx.x;
    const int tx = tid & 15;      // column group (keys / dims)
    const int ty = tid >> 4;      // row group (queries)
    const int b  = blockIdx.y;
    const int q0 = blockIdx.x * TM;

    const float beta = __ldg(betap);
    const float* xb   = x   + (size_t)b * NN * DD;
    const float* adjb = adj + (size_t)b * NN * NN;

    // ---- load Q tile, store transposed ----
    {
        int q = tid;
        #pragma unroll
        for (int it = 0; it < 4; ++it, q += 256) {
            int row = q >> 4;
            int c4  = (q & 15) << 2;
            float4 v = *(const float4*)&xb[(size_t)(q0 + row) * DD + c4];
            sQt[(c4 + 0) * PITCH + row] = v.x;
            sQt[(c4 + 1) * PITCH + row] = v.y;
            sQt[(c4 + 2) * PITCH + row] = v.z;
            sQt[(c4 + 3) * PITCH + row] = v.w;
        }
    }

    // beta / ||q_i||   (EPS dropped: rel effect ~1e-9, negligible)
    float4 rq4 = *(const float4*)&g_rnorm[b * NN + q0 + ty * 4];
    float cb[4] = { beta * rq4.x, beta * rq4.y, beta * rq4.z, beta * rq4.w };

    float m[4], l[4], acc[4][4];
    #pragma unroll
    for (int i = 0; i < 4; ++i) {
        m[i] = -1e30f; l[i] = 0.0f;
        #pragma unroll
        for (int j = 0; j < 4; ++j) acc[i][j] = 0.0f;
    }

    for (int kt = 0; kt < NN / TN; ++kt) {
        const int k0 = kt * TN;
        __syncthreads();   // previous iteration's readers of sKt/sV/sPt are done

        // ---- load K tile: natural (V) + transposed (Kt) ----
        {
            int q = tid;
            #pragma unroll
            for (int it = 0; it < 4; ++it, q += 256) {
                int row = q >> 4;
                int c4  = (q & 15) << 2;
                float4 v = *(const float4*)&xb[(size_t)(k0 + row) * DD + c4];
                *(float4*)&sV[row * 64 + c4] = v;
                sKt[(c4 + 0) * PITCH + row] = v.x;
                sKt[(c4 + 1) * PITCH + row] = v.y;
                sKt[(c4 + 2) * PITCH + row] = v.z;
                sKt[(c4 + 3) * PITCH + row] = v.w;
            }
        }
        __syncthreads();

        // ---- S = Q K^T  (4x4 register tile per thread) ----
        float s[4][4];
        #pragma unroll
        for (int i = 0; i < 4; ++i)
            #pragma unroll
            for (int j = 0; j < 4; ++j) s[i][j] = 0.0f;

        #pragma unroll 8
        for (int k = 0; k < 64; ++k) {
            float4 a  = *(const float4*)&sQt[k * PITCH + ty * 4];
            float4 bb = *(const float4*)&sKt[k * PITCH + tx * 4];
            float av[4] = { a.x, a.y, a.z, a.w };
            float bv[4] = { bb.x, bb.y, bb.z, bb.w };
            #pragma unroll
            for (int i = 0; i < 4; ++i)
                #pragma unroll
                for (int j = 0; j < 4; ++j)
                    s[i][j] = fmaf(av[i], bv[j], s[i][j]);
        }

        // ---- logits: beta*cos + sign mask + 10*adj ----
        float4 rk4 = *(const float4*)&g_rnorm[b * NN + k0 + tx * 4];
        float rk[4] = { rk4.x, rk4.y, rk4.z, rk4.w };

        #pragma unroll
        for (int i = 0; i < 4; ++i) {
            float4 a4 = __ldg((const float4*)&adjb[(size_t)(q0 + ty * 4 + i) * NN + k0 + tx * 4]);
            float ad[4] = { a4.x, a4.y, a4.z, a4.w };
            #pragma unroll
            for (int j = 0; j < 4; ++j) {
                float d  = s[i][j];
                float lg = d * cb[i] * rk[j];           // beta * cos
                lg = fmaf(ADJ_SCALE, ad[j], lg);
                if (d < 0.0f) lg += NEG_INF;            // sign(cos) == sign(dot)
                s[i][j] = lg;
            }
        }

        // ---- online softmax (state replicated across the 16-lane tx group) ----
        #pragma unroll
        for (int i = 0; i < 4; ++i) {
            float rmax = fmaxf(fmaxf(s[i][0], s[i][1]), fmaxf(s[i][2], s[i][3]));
            #pragma unroll
            for (int off = 1; off < 16; off <<= 1)
                rmax = fmaxf(rmax, __shfl_xor_sync(0xffffffffu, rmax, off));
            float mnew = fmaxf(m[i], rmax);
            float sc = __expf(m[i] - mnew);
            float rs = 0.0f;
            #pragma unroll
            for (int j = 0; j < 4; ++j) {
                float p = __expf(s[i][j] - mnew);
                s[i][j] = p;
                rs += p;
            }
            #pragma unroll
            for (int off = 1; off < 16; off <<= 1)
                rs += __shfl_xor_sync(0xffffffffu, rs, off);
            l[i] = l[i] * sc + rs;
            m[i] = mnew;
            #pragma unroll
            for (int j = 0; j < 4; ++j) acc[i][j] *= sc;
        }

        // ---- store P transposed (key-major) ----
        #pragma unroll
        for (int j = 0; j < 4; ++j) {
            float4 pv = make_float4(s[0][j], s[1][j], s[2][j], s[3][j]);
            *(float4*)&sPt[(tx * 4 + j) * PITCH + ty * 4] = pv;
        }
        __syncthreads();

        // ---- O += P V ----
        #pragma unroll 8
        for (int k = 0; k < 64; ++k) {
            float4 a  = *(const float4*)&sPt[k * PITCH + ty * 4];
            float4 bb = *(const float4*)&sV[k * 64 + tx * 4];
            float av[4] = { a.x, a.y, a.z, a.w };
            float bv[4] = { bb.x, bb.y, bb.z, bb.w };
            #pragma unroll
            for (int i = 0; i < 4; ++i)
                #pragma unroll
                for (int j = 0; j < 4; ++j)
                    acc[i][j] = fmaf(av[i], bv[j], acc[i][j]);
        }
    }

    // ---- epilogue: normalize and store ----
    float* ob = out + ((size_t)b * NN + q0) * DD;
    #pragma unroll
    for (int i = 0; i < 4; ++i) {
        float inv = 1.0f / l[i];
        float4 o = make_float4(acc[i][0] * inv, acc[i][1] * inv,
                               acc[i][2] * inv, acc[i][3] * inv);
        *(float4*)&ob[(size_t)(ty * 4 + i) * DD + tx * 4] = o;
    }
}

// ---------------------------------------------------------------------------
extern "C" void kernel_launch(void* const* d_in, const int* in_sizes, int n_in,
                              void* d_out, int out_size) {
    (void)in_sizes; (void)n_in; (void)out_size;
    const float* x    = (const float*)d_in[0];
    const float* adj  = (const float*)d_in[1];
    const float* beta = (const float*)d_in[2];
    float* out = (float*)d_out;

    norm_kernel<<<(BB * NN) / 8, 256>>>(x);

    cudaFuncSetAttribute(attn_kernel,
                         cudaFuncAttributeMaxDynamicSharedMemorySize, SMEM_BYTES);
    dim3 grid(NN / TM, BB);
    attn_kernel<<<grid, 256, SMEM_BYTES>>>(x, adj, beta, out);
}

// round 4
// speedup vs baseline: 2.0540x; 2.0540x over previous
#include <cuda_runtime.h>
#include <cuda_bf16.h>
#include <cstdint>

#define BB 4
#define NN 4096
#define DD 64
#define TM 128
#define TN 64
#define NTILES (NN / TN)
#define DOT_TOL 0.01f

// ---------------- device scratch (allocation-free) ----------------
__device__ __align__(16) __nv_bfloat16 g_xhi [BB * NN * DD];   // row-major hi
__device__ __align__(16) __nv_bfloat16 g_xlo [BB * NN * DD];   // row-major lo
__device__ __align__(16) __nv_bfloat16 g_xThi[BB * DD * NN];   // transposed hi [b][d][n]
__device__ __align__(16) __nv_bfloat16 g_xTlo[BB * DD * NN];   // transposed lo
__device__ __align__(16) float g_rn [BB * NN];                 // 1/||x||
__device__ __align__(16) float g_rnb[BB * NN];                 // beta/||x||

// ---------------- helpers ----------------
__device__ __forceinline__ uint32_t smem_u32(const void* p) {
    uint32_t a;
    asm("{ .reg .u64 t; cvta.to.shared.u64 t, %1; cvt.u32.u64 %0, t; }" : "=r"(a) : "l"(p));
    return a;
}
#define SW(o) ((o) ^ (((o) >> 3) & 0x70))
#define CPA(dst, src) asm volatile("cp.async.cg.shared.global [%0], [%1], 16;" :: "r"(dst), "l"(src))
#define CPC()   asm volatile("cp.async.commit_group;" ::: "memory")
#define CPW0()  asm volatile("cp.async.wait_group 0;" ::: "memory")

__device__ __forceinline__ void ldsm4(uint32_t& r0, uint32_t& r1, uint32_t& r2, uint32_t& r3, uint32_t a) {
    asm volatile("ldmatrix.sync.aligned.m8n8.x4.shared.b16 {%0,%1,%2,%3}, [%4];"
                 : "=r"(r0), "=r"(r1), "=r"(r2), "=r"(r3) : "r"(a));
}
__device__ __forceinline__ void mma16816(float* d, const uint32_t* a, const uint32_t* b) {
    asm volatile("mma.sync.aligned.m16n8k16.row.col.f32.bf16.bf16.f32 "
                 "{%0,%1,%2,%3}, {%4,%5,%6,%7}, {%8,%9}, {%0,%1,%2,%3};"
                 : "+f"(d[0]), "+f"(d[1]), "+f"(d[2]), "+f"(d[3])
                 : "r"(a[0]), "r"(a[1]), "r"(a[2]), "r"(a[3]), "r"(b[0]), "r"(b[1]));
}
__device__ __forceinline__ uint32_t pack2(__nv_bfloat16 a, __nv_bfloat16 b) {
    return (uint32_t)__bfloat16_as_ushort(a) | ((uint32_t)__bfloat16_as_ushort(b) << 16);
}

// cold-path exact fp32 dot (sign rescue for near-zero neighbor logits)
__device__ __noinline__ float dot64(const float* __restrict__ a, const float* __restrict__ b) {
    float acc = 0.f;
    #pragma unroll
    for (int i = 0; i < 16; ++i) {
        float4 va = __ldg((const float4*)a + i);
        float4 vb = __ldg((const float4*)b + i);
        acc = fmaf(va.x, vb.x, acc); acc = fmaf(va.y, vb.y, acc);
        acc = fmaf(va.z, vb.z, acc); acc = fmaf(va.w, vb.w, acc);
    }
    return acc;
}

// ---------------- prep: norms + bf16 hi/lo (row-major + transposed) ----------------
__global__ __launch_bounds__(256) void prep_kernel(const float* __restrict__ x,
                                                   const float* __restrict__ betap) {
    __shared__ float s[64][68];
    const int row0 = blockIdx.x * 64;
    const int tid = threadIdx.x;

    for (int i = tid; i < 64 * 16; i += 256) {
        int r = i >> 4, c4 = (i & 15) << 2;
        float4 v = *(const float4*)&x[(size_t)(row0 + r) * DD + c4];
        s[r][c4] = v.x; s[r][c4 + 1] = v.y; s[r][c4 + 2] = v.z; s[r][c4 + 3] = v.w;
    }
    __syncthreads();

    const float beta = __ldg(betap);
    if (tid < 64) {
        float acc = 0.f;
        #pragma unroll
        for (int d = 0; d < 64; ++d) acc = fmaf(s[tid][d], s[tid][d], acc);
        float rn = 1.0f / sqrtf(acc);
        g_rn[row0 + tid] = rn;
        g_rnb[row0 + tid] = beta * rn;
    }

    // row-major hi/lo
    {
        int base = tid * 16;
        int r = base >> 6, c = base & 63;
        uint32_t hb[8], lb[8];
        #pragma unroll
        for (int j = 0; j < 8; ++j) {
            float a = s[r][c + 2 * j], b = s[r][c + 2 * j + 1];
            __nv_bfloat16 ah = __float2bfloat16(a), bh = __float2bfloat16(b);
            __nv_bfloat16 al = __float2bfloat16(a - __bfloat162float(ah));
            __nv_bfloat16 bl = __float2bfloat16(b - __bfloat162float(bh));
            hb[j] = pack2(ah, bh); lb[j] = pack2(al, bl);
        }
        uint4* dh = (uint4*)(g_xhi + (size_t)row0 * DD + base);
        uint4* dl = (uint4*)(g_xlo + (size_t)row0 * DD + base);
        dh[0] = make_uint4(hb[0], hb[1], hb[2], hb[3]); dh[1] = make_uint4(hb[4], hb[5], hb[6], hb[7]);
        dl[0] = make_uint4(lb[0], lb[1], lb[2], lb[3]); dl[1] = make_uint4(lb[4], lb[5], lb[6], lb[7]);
    }
    // transposed hi/lo
    {
        int d = tid >> 2, j0 = (tid & 3) * 16;
        int b = row0 / NN, n0 = row0 % NN;
        uint32_t hb[8], lb[8];
        #pragma unroll
        for (int j = 0; j < 8; ++j) {
            float a = s[j0 + 2 * j][d], bb = s[j0 + 2 * j + 1][d];
            __nv_bfloat16 ah = __float2bfloat16(a), bh = __float2bfloat16(bb);
            __nv_bfloat16 al = __float2bfloat16(a - __bfloat162float(ah));
            __nv_bfloat16 bl = __float2bfloat16(bb - __bfloat162float(bh));
            hb[j] = pack2(ah, bh); lb[j] = pack2(al, bl);
        }
        size_t off = (size_t)(b * DD + d) * NN + n0 + j0;
        uint4* dh = (uint4*)(g_xThi + off);
        uint4* dl = (uint4*)(g_xTlo + off);
        dh[0] = make_uint4(hb[0], hb[1], hb[2], hb[3]); dh[1] = make_uint4(hb[4], hb[5], hb[6], hb[7]);
        dl[0] = make_uint4(lb[0], lb[1], lb[2], lb[3]); dl[1] = make_uint4(lb[4], lb[5], lb[6], lb[7]);
    }
}

// ---------------- smem layout ----------------
#define OFF_Q   0
#define OFF_ST  32768
#define SMEM_TOTAL (32768 + 2 * 32768)

__device__ __forceinline__ void load_stage(uint32_t stbase, int tid, int b, int k0) {
    const __nv_bfloat16* kh = g_xhi + ((size_t)b * NN + k0) * DD;
    const __nv_bfloat16* kl = g_xlo + ((size_t)b * NN + k0) * DD;
    const __nv_bfloat16* vh = g_xThi + (size_t)b * DD * NN + k0;
    const __nv_bfloat16* vl = g_xTlo + (size_t)b * DD * NN + k0;
    #pragma unroll
    for (int it = 0; it < 8; ++it) {
        int m = tid + it * 256;
        int buf = m >> 9, idx = m & 511, r = idx >> 3, c = idx & 7;
        uint32_t dst = stbase + buf * 8192 + SW(r * 128 + c * 16);
        const __nv_bfloat16* src;
        if (buf == 0)      src = kh + r * 64 + c * 8;
        else if (buf == 1) src = kl + r * 64 + c * 8;
        else if (buf == 2) src = vh + (size_t)r * NN + c * 8;
        else               src = vl + (size_t)r * NN + c * 8;
        CPA(dst, src);
    }
}

// ---------------- main kernel ----------------
__global__ __launch_bounds__(256, 1)
void attn_mma(const float* __restrict__ x,
              const float* __restrict__ adj,
              const float* __restrict__ betap,
              float* __restrict__ out) {
    extern __shared__ char smem[];
    const uint32_t sb = smem_u32(smem);
    const int tid = threadIdx.x;
    const int wid = tid >> 5, lane = tid & 31;
    const int g = lane >> 2, t = lane & 3;
    const int b = blockIdx.y, q0 = blockIdx.x * TM;
    const size_t bNN = (size_t)b * NN;

    const int lm = lane >> 3, li = lane & 7;
    const uint32_t b_row = ((lm >> 1) << 3) + li;
    const uint32_t b_kb  = (uint32_t)(lm & 1) << 4;
    const uint32_t a_row = ((uint32_t)(lm & 1) << 3) + li + wid * 16;
    const uint32_t a_kb  = (uint32_t)(lm >> 1) << 4;

    // prologue: Q hi/lo + tile0
    {
        const __nv_bfloat16* qh = g_xhi + (bNN + q0) * DD;
        const __nv_bfloat16* ql = g_xlo + (bNN + q0) * DD;
        #pragma unroll
        for (int it = 0; it < 8; ++it) {
            int m = tid + it * 256;
            int buf = m >> 10, idx = m & 1023, r = idx >> 3, c = idx & 7;
            const __nv_bfloat16* src = (buf ? ql : qh) + r * 64 + c * 8;
            CPA(sb + OFF_Q + buf * 16384 + SW(r * 128 + c * 16), src);
        }
        load_stage(sb + OFF_ST, tid, b, 0);
        CPC();
    }

    const float beta = __ldg(betap);
    const float C = beta + 10.0f;
    const float rq0 = g_rn[bNN + q0 + wid * 16 + g];
    const float rq1 = g_rn[bNN + q0 + wid * 16 + g + 8];
    const float* adjrow = adj + (bNN + q0 + wid * 16 + g) * (size_t)NN + 2 * t;
    const float* xb  = x + bNN * DD;
    const float* xq0 = xb + (size_t)(q0 + wid * 16 + g) * DD;
    const float* xq1 = xq0 + 8 * DD;

    uint32_t qhiF[4][4], qloF[4][4];
    float o[8][4];
    #pragma unroll
    for (int j = 0; j < 8; ++j)
        { o[j][0] = 0.f; o[j][1] = 0.f; o[j][2] = 0.f; o[j][3] = 0.f; }
    float lsum0 = 0.f, lsum1 = 0.f;

    for (int tt = 0; tt < NTILES; ++tt) {
        const int k0 = tt * TN;
        CPW0();
        __syncthreads();
        if (tt + 1 < NTILES) {
            load_stage(sb + OFF_ST + ((tt + 1) & 1) * 32768, tid, b, k0 + TN);
            CPC();
        }
        if (tt == 0) {
            #pragma unroll
            for (int ks = 0; ks < 4; ++ks) {
                uint32_t ad = sb + OFF_Q + SW(a_row * 128 + ks * 32 + a_kb);
                ldsm4(qhiF[ks][0], qhiF[ks][1], qhiF[ks][2], qhiF[ks][3], ad);
                ldsm4(qloF[ks][0], qloF[ks][1], qloF[ks][2], qloF[ks][3], ad + 16384);
            }
        }
        const uint32_t stb = sb + OFF_ST + (tt & 1) * 32768;

        // adj prefetch (overlaps with the S mma)
        float2 av0[8], av1[8];
        {
            const float* ar0 = adjrow + k0;
            const float* ar1 = ar0 + (size_t)8 * NN;
            #pragma unroll
            for (int j = 0; j < 8; ++j) {
                av0[j] = __ldg((const float2*)(ar0 + 8 * j));
                av1[j] = __ldg((const float2*)(ar1 + 8 * j));
            }
        }

        // ---- S = Q K^T : 4-term bf16 split ----
        float s[8][4];
        #pragma unroll
        for (int j = 0; j < 8; ++j)
            { s[j][0] = 0.f; s[j][1] = 0.f; s[j][2] = 0.f; s[j][3] = 0.f; }

        #pragma unroll
        for (int ks = 0; ks < 4; ++ks) {
            uint32_t bf[8][2];
            #pragma unroll
            for (int nb = 0; nb < 4; ++nb) {
                uint32_t ad = stb + SW((nb * 16 + b_row) * 128 + ks * 32 + b_kb);
                ldsm4(bf[2 * nb][0], bf[2 * nb][1], bf[2 * nb + 1][0], bf[2 * nb + 1][1], ad);
            }
            #pragma unroll
            for (int j = 0; j < 8; ++j) { mma16816(s[j], qhiF[ks], bf[j]); mma16816(s[j], qloF[ks], bf[j]); }
            #pragma unroll
            for (int nb = 0; nb < 4; ++nb) {
                uint32_t ad = stb + 8192 + SW((nb * 16 + b_row) * 128 + ks * 32 + b_kb);
                ldsm4(bf[2 * nb][0], bf[2 * nb][1], bf[2 * nb + 1][0], bf[2 * nb + 1][1], ad);
            }
            #pragma unroll
            for (int j = 0; j < 8; ++j) { mma16816(s[j], qhiF[ks], bf[j]); mma16816(s[j], qloF[ks], bf[j]); }
        }

        // ---- logits -> exp -> pack P ----
        uint32_t ahi[4][4], alo[4][4];
        {
            const float* rnbp = g_rnb + bNN + k0 + 2 * t;
            #pragma unroll
            for (int j = 0; j < 8; ++j) {
                // cold fp32 sign rescue: adj=1 entries with |dot| in the MMA error band
                {
                    bool n0 = (av0[j].x > 0.5f) && (fabsf(s[j][0]) < DOT_TOL);
                    bool n1 = (av0[j].y > 0.5f) && (fabsf(s[j][1]) < DOT_TOL);
                    bool n2 = (av1[j].x > 0.5f) && (fabsf(s[j][2]) < DOT_TOL);
                    bool n3 = (av1[j].y > 0.5f) && (fabsf(s[j][3]) < DOT_TOL);
                    if (n0 | n1 | n2 | n3) {
                        const int kk = k0 + 8 * j + 2 * t;
                        if (n0) s[j][0] = dot64(xq0, xb + (size_t)kk * DD);
                        if (n1) s[j][1] = dot64(xq0, xb + (size_t)(kk + 1) * DD);
                        if (n2) s[j][2] = dot64(xq1, xb + (size_t)kk * DD);
                        if (n3) s[j][3] = dot64(xq1, xb + (size_t)(kk + 1) * DD);
                    }
                }
                float2 rk = __ldg((const float2*)(rnbp + 8 * j));
                float r00 = rq0 * rk.x, r01 = rq0 * rk.y;
                float r10 = rq1 * rk.x, r11 = rq1 * rk.y;
                float lg0 = (s[j][0] < 0.f) ? -1e30f : fmaf(10.f, av0[j].x, fmaf(s[j][0], r00, -C));
                float lg1 = (s[j][1] < 0.f) ? -1e30f : fmaf(10.f, av0[j].y, fmaf(s[j][1], r01, -C));
                float lg2 = (s[j][2] < 0.f) ? -1e30f : fmaf(10.f, av1[j].x, fmaf(s[j][2], r10, -C));
                float lg3 = (s[j][3] < 0.f) ? -1e30f : fmaf(10.f, av1[j].y, fmaf(s[j][3], r11, -C));
                float p0 = __expf(lg0), p1 = __expf(lg1), p2 = __expf(lg2), p3 = __expf(lg3);
                lsum0 += p0 + p1; lsum1 += p2 + p3;
                uint32_t h01, h23;
                asm("cvt.rn.bf16x2.f32 %0, %1, %2;" : "=r"(h01) : "f"(p1), "f"(p0));
                asm("cvt.rn.bf16x2.f32 %0, %1, %2;" : "=r"(h23) : "f"(p3), "f"(p2));
                float hf0 = __uint_as_float(h01 << 16), hf1 = __uint_as_float(h01 & 0xFFFF0000u);
                float hf2 = __uint_as_float(h23 << 16), hf3 = __uint_as_float(h23 & 0xFFFF0000u);
                uint32_t l01, l23;
                asm("cvt.rn.bf16x2.f32 %0, %1, %2;" : "=r"(l01) : "f"(p1 - hf1), "f"(p0 - hf0));
                asm("cvt.rn.bf16x2.f32 %0, %1, %2;" : "=r"(l23) : "f"(p3 - hf3), "f"(p2 - hf2));
                int cc = j >> 1, h = (j & 1) << 1;
                ahi[cc][h] = h01; ahi[cc][h + 1] = h23;
                alo[cc][h] = l01; alo[cc][h + 1] = l23;
            }
        }

        // ---- O += P V : 3-term split ----
        #pragma unroll
        for (int c = 0; c < 4; ++c) {
            uint32_t bf[8][2];
            #pragma unroll
            for (int nb = 0; nb < 4; ++nb) {
                uint32_t ad = stb + 16384 + SW((nb * 16 + b_row) * 128 + c * 32 + b_kb);
                ldsm4(bf[2 * nb][0], bf[2 * nb][1], bf[2 * nb + 1][0], bf[2 * nb + 1][1], ad);
            }
            #pragma unroll
            for (int j = 0; j < 8; ++j) { mma16816(o[j], ahi[c], bf[j]); mma16816(o[j], alo[c], bf[j]); }
            #pragma unroll
            for (int nb = 0; nb < 4; ++nb) {
                uint32_t ad = stb + 24576 + SW((nb * 16 + b_row) * 128 + c * 32 + b_kb);
                ldsm4(bf[2 * nb][0], bf[2 * nb][1], bf[2 * nb + 1][0], bf[2 * nb + 1][1], ad);
            }
            #pragma unroll
            for (int j = 0; j < 8; ++j) { mma16816(o[j], ahi[c], bf[j]); }
        }
    }

    // ---- epilogue ----
    lsum0 += __shfl_xor_sync(0xffffffffu, lsum0, 1);
    lsum0 += __shfl_xor_sync(0xffffffffu, lsum0, 2);
    lsum1 += __shfl_xor_sync(0xffffffffu, lsum1, 1);
    lsum1 += __shfl_xor_sync(0xffffffffu, lsum1, 2);
    const float inv0 = 1.0f / lsum0;
    const float inv1 = 1.0f / lsum1;

    float* o0 = out + (bNN + q0 + wid * 16 + g) * DD + 2 * t;
    float* o1 = o0 + 8 * DD;
    #pragma unroll
    for (int j = 0; j < 8; ++j) {
        *(float2*)(o0 + 8 * j) = make_float2(o[j][0] * inv0, o[j][1] * inv0);
        *(float2*)(o1 + 8 * j) = make_float2(o[j][2] * inv1, o[j][3] * inv1);
    }
}

// ---------------------------------------------------------------------------
extern "C" void kernel_launch(void* const* d_in, const int* in_sizes, int n_in,
                              void* d_out, int out_size) {
    (void)in_sizes; (void)n_in; (void)out_size;
    const float* x    = (const float*)d_in[0];
    const float* adj  = (const float*)d_in[1];
    const float* beta = (const float*)d_in[2];
    float* out = (float*)d_out;

    prep_kernel<<<BB * NN / 64, 256>>>(x, beta);

    cudaFuncSetAttribute(attn_mma, cudaFuncAttributeMaxDynamicSharedMemorySize, SMEM_TOTAL);
    dim3 grid(NN / TM, BB);
    attn_mma<<<grid, 256, SMEM_TOTAL>>>(x, adj, beta, out);
}

// round 5
// speedup vs baseline: 2.3426x; 1.1405x over previous
#include <cuda_runtime.h>
#include <cuda_bf16.h>
#include <cstdint>

#define BB 4
#define NN 4096
#define DD 64
#define TM 64
#define TN 64
#define NTILES (NN / TN)
#define DOT_TOL 0.02f

// ---------------- device scratch (allocation-free) ----------------
__device__ __align__(16) __nv_bfloat16 g_xhi [BB * NN * DD];   // row-major hi
__device__ __align__(16) __nv_bfloat16 g_xlo [BB * NN * DD];   // row-major lo
__device__ __align__(16) __nv_bfloat16 g_xThi[BB * DD * NN];   // transposed hi [b][d][n]
__device__ __align__(16) __nv_bfloat16 g_xTlo[BB * DD * NN];   // transposed lo
__device__ __align__(16) float g_rn [BB * NN];                 // 1/||x||
__device__ __align__(16) float g_rnb[BB * NN];                 // beta/||x||

// ---------------- helpers ----------------
__device__ __forceinline__ uint32_t smem_u32(const void* p) {
    uint32_t a;
    asm("{ .reg .u64 t; cvta.to.shared.u64 t, %1; cvt.u32.u64 %0, t; }" : "=r"(a) : "l"(p));
    return a;
}
#define SW(o) ((o) ^ (((o) >> 3) & 0x70))
#define CPA(dst, src) asm volatile("cp.async.cg.shared.global [%0], [%1], 16;" :: "r"(dst), "l"(src))
#define CPC()   asm volatile("cp.async.commit_group;" ::: "memory")
#define CPW0()  asm volatile("cp.async.wait_group 0;" ::: "memory")

__device__ __forceinline__ void ldsm4(uint32_t& r0, uint32_t& r1, uint32_t& r2, uint32_t& r3, uint32_t a) {
    asm volatile("ldmatrix.sync.aligned.m8n8.x4.shared.b16 {%0,%1,%2,%3}, [%4];"
                 : "=r"(r0), "=r"(r1), "=r"(r2), "=r"(r3) : "r"(a));
}
__device__ __forceinline__ void mma16816(float* d, const uint32_t* a, const uint32_t* b) {
    asm volatile("mma.sync.aligned.m16n8k16.row.col.f32.bf16.bf16.f32 "
                 "{%0,%1,%2,%3}, {%4,%5,%6,%7}, {%8,%9}, {%0,%1,%2,%3};"
                 : "+f"(d[0]), "+f"(d[1]), "+f"(d[2]), "+f"(d[3])
                 : "r"(a[0]), "r"(a[1]), "r"(a[2]), "r"(a[3]), "r"(b[0]), "r"(b[1]));
}
__device__ __forceinline__ uint32_t pack2(__nv_bfloat16 a, __nv_bfloat16 b) {
    return (uint32_t)__bfloat16_as_ushort(a) | ((uint32_t)__bfloat16_as_ushort(b) << 16);
}

// cold-path exact fp32 dot (sign rescue for near-zero neighbor logits)
__device__ __noinline__ float dot64(const float* __restrict__ a, const float* __restrict__ b) {
    float acc = 0.f;
    #pragma unroll
    for (int i = 0; i < 16; ++i) {
        float4 va = __ldg((const float4*)a + i);
        float4 vb = __ldg((const float4*)b + i);
        acc = fmaf(va.x, vb.x, acc); acc = fmaf(va.y, vb.y, acc);
        acc = fmaf(va.z, vb.z, acc); acc = fmaf(va.w, vb.w, acc);
    }
    return acc;
}

// ---------------- prep: norms + bf16 hi/lo (row-major + transposed) ----------------
__global__ __launch_bounds__(256) void prep_kernel(const float* __restrict__ x,
                                                   const float* __restrict__ betap) {
    __shared__ float s[64][68];
    const int row0 = blockIdx.x * 64;
    const int tid = threadIdx.x;

    for (int i = tid; i < 64 * 16; i += 256) {
        int r = i >> 4, c4 = (i & 15) << 2;
        float4 v = *(const float4*)&x[(size_t)(row0 + r) * DD + c4];
        s[r][c4] = v.x; s[r][c4 + 1] = v.y; s[r][c4 + 2] = v.z; s[r][c4 + 3] = v.w;
    }
    __syncthreads();

    const float beta = __ldg(betap);
    if (tid < 64) {
        float acc = 0.f;
        #pragma unroll
        for (int d = 0; d < 64; ++d) acc = fmaf(s[tid][d], s[tid][d], acc);
        float rn = 1.0f / sqrtf(acc);
        g_rn[row0 + tid] = rn;
        g_rnb[row0 + tid] = beta * rn;
    }

    // row-major hi/lo
    {
        int base = tid * 16;
        int r = base >> 6, c = base & 63;
        uint32_t hb[8], lb[8];
        #pragma unroll
        for (int j = 0; j < 8; ++j) {
            float a = s[r][c + 2 * j], b = s[r][c + 2 * j + 1];
            __nv_bfloat16 ah = __float2bfloat16(a), bh = __float2bfloat16(b);
            __nv_bfloat16 al = __float2bfloat16(a - __bfloat162float(ah));
            __nv_bfloat16 bl = __float2bfloat16(b - __bfloat162float(bh));
            hb[j] = pack2(ah, bh); lb[j] = pack2(al, bl);
        }
        uint4* dh = (uint4*)(g_xhi + (size_t)row0 * DD + base);
        uint4* dl = (uint4*)(g_xlo + (size_t)row0 * DD + base);
        dh[0] = make_uint4(hb[0], hb[1], hb[2], hb[3]); dh[1] = make_uint4(hb[4], hb[5], hb[6], hb[7]);
        dl[0] = make_uint4(lb[0], lb[1], lb[2], lb[3]); dl[1] = make_uint4(lb[4], lb[5], lb[6], lb[7]);
    }
    // transposed hi/lo
    {
        int d = tid >> 2, j0 = (tid & 3) * 16;
        int b = row0 / NN, n0 = row0 % NN;
        uint32_t hb[8], lb[8];
        #pragma unroll
        for (int j = 0; j < 8; ++j) {
            float a = s[j0 + 2 * j][d], bb = s[j0 + 2 * j + 1][d];
            __nv_bfloat16 ah = __float2bfloat16(a), bh = __float2bfloat16(bb);
            __nv_bfloat16 al = __float2bfloat16(a - __bfloat162float(ah));
            __nv_bfloat16 bl = __float2bfloat16(bb - __bfloat162float(bh));
            hb[j] = pack2(ah, bh); lb[j] = pack2(al, bl);
        }
        size_t off = (size_t)(b * DD + d) * NN + n0 + j0;
        uint4* dh = (uint4*)(g_xThi + off);
        uint4* dl = (uint4*)(g_xTlo + off);
        dh[0] = make_uint4(hb[0], hb[1], hb[2], hb[3]); dh[1] = make_uint4(hb[4], hb[5], hb[6], hb[7]);
        dl[0] = make_uint4(lb[0], lb[1], lb[2], lb[3]); dl[1] = make_uint4(lb[4], lb[5], lb[6], lb[7]);
    }
}

// ---------------- smem layout ----------------
// Q: hi 8K + lo 8K; stages: 2 x (Khi 8K | Klo 8K | Vhi 8K | Vlo 8K)
#define OFF_Q   0
#define OFF_ST  16384
#define SMEM_TOTAL (16384 + 2 * 32768)

__device__ __forceinline__ void load_stage(uint32_t stbase, int tid, int b, int k0) {
    const __nv_bfloat16* kh = g_xhi + ((size_t)b * NN + k0) * DD;
    const __nv_bfloat16* kl = g_xlo + ((size_t)b * NN + k0) * DD;
    const __nv_bfloat16* vh = g_xThi + (size_t)b * DD * NN + k0;
    const __nv_bfloat16* vl = g_xTlo + (size_t)b * DD * NN + k0;
    #pragma unroll
    for (int it = 0; it < 16; ++it) {
        int m = tid + it * 128;
        int buf = m >> 9, idx = m & 511, r = idx >> 3, c = idx & 7;
        uint32_t dst = stbase + buf * 8192 + SW(r * 128 + c * 16);
        const __nv_bfloat16* src;
        if (buf == 0)      src = kh + r * 64 + c * 8;
        else if (buf == 1) src = kl + r * 64 + c * 8;
        else if (buf == 2) src = vh + (size_t)r * NN + c * 8;
        else               src = vl + (size_t)r * NN + c * 8;
        CPA(dst, src);
    }
}

// ---------------- main kernel: 128 threads, 2 CTAs/SM ----------------
__global__ __launch_bounds__(128, 2)
void attn_mma(const float* __restrict__ x,
              const float* __restrict__ adj,
              const float* __restrict__ betap,
              float* __restrict__ out) {
    extern __shared__ char smem[];
    const uint32_t sb = smem_u32(smem);
    const int tid = threadIdx.x;
    const int wid = tid >> 5, lane = tid & 31;
    const int g = lane >> 2, t = lane & 3;
    const int b = blockIdx.y, q0 = blockIdx.x * TM;
    const size_t bNN = (size_t)b * NN;

    const int lm = lane >> 3, li = lane & 7;
    const uint32_t b_row = ((lm >> 1) << 3) + li;
    const uint32_t b_kb  = (uint32_t)(lm & 1) << 4;
    const uint32_t a_row = ((uint32_t)(lm & 1) << 3) + li + wid * 16;
    const uint32_t a_kb  = (uint32_t)(lm >> 1) << 4;

    // prologue: Q hi/lo (64 rows) + tile0
    {
        const __nv_bfloat16* qh = g_xhi + (bNN + q0) * DD;
        const __nv_bfloat16* ql = g_xlo + (bNN + q0) * DD;
        #pragma unroll
        for (int it = 0; it < 8; ++it) {
            int m = tid + it * 128;
            int buf = m >> 9, idx = m & 511, r = idx >> 3, c = idx & 7;
            const __nv_bfloat16* src = (buf ? ql : qh) + r * 64 + c * 8;
            CPA(sb + OFF_Q + buf * 8192 + SW(r * 128 + c * 16), src);
        }
        load_stage(sb + OFF_ST, tid, b, 0);
        CPC();
    }

    const float beta = __ldg(betap);
    const float C = beta + 10.0f;
    const float rq0 = g_rn[bNN + q0 + wid * 16 + g];
    const float rq1 = g_rn[bNN + q0 + wid * 16 + g + 8];
    const float* adjrow = adj + (bNN + q0 + wid * 16 + g) * (size_t)NN + 2 * t;
    const float* xb  = x + bNN * DD;
    const float* xq0 = xb + (size_t)(q0 + wid * 16 + g) * DD;
    const float* xq1 = xq0 + 8 * DD;

    uint32_t qhiF[4][4], qloF[4][4];
    float o[8][4];
    #pragma unroll
    for (int j = 0; j < 8; ++j)
        { o[j][0] = 0.f; o[j][1] = 0.f; o[j][2] = 0.f; o[j][3] = 0.f; }
    float lsum0 = 0.f, lsum1 = 0.f;

    for (int tt = 0; tt < NTILES; ++tt) {
        const int k0 = tt * TN;
        CPW0();
        __syncthreads();
        if (tt + 1 < NTILES) {
            load_stage(sb + OFF_ST + ((tt + 1) & 1) * 32768, tid, b, k0 + TN);
            CPC();
        }
        if (tt == 0) {
            #pragma unroll
            for (int ks = 0; ks < 4; ++ks) {
                uint32_t ad = sb + OFF_Q + SW(a_row * 128 + ks * 32 + a_kb);
                ldsm4(qhiF[ks][0], qhiF[ks][1], qhiF[ks][2], qhiF[ks][3], ad);
                ldsm4(qloF[ks][0], qloF[ks][1], qloF[ks][2], qloF[ks][3], ad + 8192);
            }
        }
        const uint32_t stb = sb + OFF_ST + (tt & 1) * 32768;

        // adj prefetch (overlaps with the S mma)
        float2 av0[8], av1[8];
        {
            const float* ar0 = adjrow + k0;
            const float* ar1 = ar0 + (size_t)8 * NN;
            #pragma unroll
            for (int j = 0; j < 8; ++j) {
                av0[j] = __ldg((const float2*)(ar0 + 8 * j));
                av1[j] = __ldg((const float2*)(ar1 + 8 * j));
            }
        }

        // ---- S = Q K^T : 3-term bf16 split (lo*lo dropped; rescue covers) ----
        float s[8][4];
        #pragma unroll
        for (int j = 0; j < 8; ++j)
            { s[j][0] = 0.f; s[j][1] = 0.f; s[j][2] = 0.f; s[j][3] = 0.f; }

        #pragma unroll
        for (int ks = 0; ks < 4; ++ks) {
            uint32_t bf[8][2];
            #pragma unroll
            for (int nb = 0; nb < 4; ++nb) {
                uint32_t ad = stb + SW((nb * 16 + b_row) * 128 + ks * 32 + b_kb);
                ldsm4(bf[2 * nb][0], bf[2 * nb][1], bf[2 * nb + 1][0], bf[2 * nb + 1][1], ad);
            }
            #pragma unroll
            for (int j = 0; j < 8; ++j) { mma16816(s[j], qhiF[ks], bf[j]); mma16816(s[j], qloF[ks], bf[j]); }
            #pragma unroll
            for (int nb = 0; nb < 4; ++nb) {
                uint32_t ad = stb + 8192 + SW((nb * 16 + b_row) * 128 + ks * 32 + b_kb);
                ldsm4(bf[2 * nb][0], bf[2 * nb][1], bf[2 * nb + 1][0], bf[2 * nb + 1][1], ad);
            }
            #pragma unroll
            for (int j = 0; j < 8; ++j) { mma16816(s[j], qhiF[ks], bf[j]); }
        }

        // ---- logits -> exp -> pack P ----
        uint32_t ahi[4][4], alo[4][4];
        {
            const float* rnbp = g_rnb + bNN + k0 + 2 * t;
            #pragma unroll
            for (int j = 0; j < 8; ++j) {
                // cold fp32 sign rescue: adj=1 entries with |dot| in the MMA error band
                {
                    bool n0 = (av0[j].x > 0.5f) && (fabsf(s[j][0]) < DOT_TOL);
                    bool n1 = (av0[j].y > 0.5f) && (fabsf(s[j][1]) < DOT_TOL);
                    bool n2 = (av1[j].x > 0.5f) && (fabsf(s[j][2]) < DOT_TOL);
                    bool n3 = (av1[j].y > 0.5f) && (fabsf(s[j][3]) < DOT_TOL);
                    if (n0 | n1 | n2 | n3) {
                        const int kk = k0 + 8 * j + 2 * t;
                        if (n0) s[j][0] = dot64(xq0, xb + (size_t)kk * DD);
                        if (n1) s[j][1] = dot64(xq0, xb + (size_t)(kk + 1) * DD);
                        if (n2) s[j][2] = dot64(xq1, xb + (size_t)kk * DD);
                        if (n3) s[j][3] = dot64(xq1, xb + (size_t)(kk + 1) * DD);
                    }
                }
                float2 rk = __ldg((const float2*)(rnbp + 8 * j));
                float r00 = rq0 * rk.x, r01 = rq0 * rk.y;
                float r10 = rq1 * rk.x, r11 = rq1 * rk.y;
                float lg0 = (s[j][0] < 0.f) ? -1e30f : fmaf(10.f, av0[j].x, fmaf(s[j][0], r00, -C));
                float lg1 = (s[j][1] < 0.f) ? -1e30f : fmaf(10.f, av0[j].y, fmaf(s[j][1], r01, -C));
                float lg2 = (s[j][2] < 0.f) ? -1e30f : fmaf(10.f, av1[j].x, fmaf(s[j][2], r10, -C));
                float lg3 = (s[j][3] < 0.f) ? -1e30f : fmaf(10.f, av1[j].y, fmaf(s[j][3], r11, -C));
                float p0 = __expf(lg0), p1 = __expf(lg1), p2 = __expf(lg2), p3 = __expf(lg3);
                lsum0 += p0 + p1; lsum1 += p2 + p3;
                uint32_t h01, h23;
                asm("cvt.rn.bf16x2.f32 %0, %1, %2;" : "=r"(h01) : "f"(p1), "f"(p0));
                asm("cvt.rn.bf16x2.f32 %0, %1, %2;" : "=r"(h23) : "f"(p3), "f"(p2));
                float hf0 = __uint_as_float(h01 << 16), hf1 = __uint_as_float(h01 & 0xFFFF0000u);
                float hf2 = __uint_as_float(h23 << 16), hf3 = __uint_as_float(h23 & 0xFFFF0000u);
                uint32_t l01, l23;
                asm("cvt.rn.bf16x2.f32 %0, %1, %2;" : "=r"(l01) : "f"(p1 - hf1), "f"(p0 - hf0));
                asm("cvt.rn.bf16x2.f32 %0, %1, %2;" : "=r"(l23) : "f"(p3 - hf3), "f"(p2 - hf2));
                int cc = j >> 1, h = (j & 1) << 1;
                ahi[cc][h] = h01; ahi[cc][h + 1] = h23;
                alo[cc][h] = l01; alo[cc][h + 1] = l23;
            }
        }

        // ---- O += P V : 3-term split ----
        #pragma unroll
        for (int c = 0; c < 4; ++c) {
            uint32_t bf[8][2];
            #pragma unroll
            for (int nb = 0; nb < 4; ++nb) {
                uint32_t ad = stb + 16384 + SW((nb * 16 + b_row) * 128 + c * 32 + b_kb);
                ldsm4(bf[2 * nb][0], bf[2 * nb][1], bf[2 * nb + 1][0], bf[2 * nb + 1][1], ad);
            }
            #pragma unroll
            for (int j = 0; j < 8; ++j) { mma16816(o[j], ahi[c], bf[j]); mma16816(o[j], alo[c], bf[j]); }
            #pragma unroll
            for (int nb = 0; nb < 4; ++nb) {
                uint32_t ad = stb + 24576 + SW((nb * 16 + b_row) * 128 + c * 32 + b_kb);
                ldsm4(bf[2 * nb][0], bf[2 * nb][1], bf[2 * nb + 1][0], bf[2 * nb + 1][1], ad);
            }
            #pragma unroll
            for (int j = 0; j < 8; ++j) { mma16816(o[j], ahi[c], bf[j]); }
        }
    }

    // ---- epilogue ----
    lsum0 += __shfl_xor_sync(0xffffffffu, lsum0, 1);
    lsum0 += __shfl_xor_sync(0xffffffffu, lsum0, 2);
    lsum1 += __shfl_xor_sync(0xffffffffu, lsum1, 1);
    lsum1 += __shfl_xor_sync(0xffffffffu, lsum1, 2);
    const float inv0 = 1.0f / lsum0;
    const float inv1 = 1.0f / lsum1;

    float* o0 = out + (bNN + q0 + wid * 16 + g) * DD + 2 * t;
    float* o1 = o0 + 8 * DD;
    #pragma unroll
    for (int j = 0; j < 8; ++j) {
        *(float2*)(o0 + 8 * j) = make_float2(o[j][0] * inv0, o[j][1] * inv0);
        *(float2*)(o1 + 8 * j) = make_float2(o[j][2] * inv1, o[j][3] * inv1);
    }
}

// ---------------------------------------------------------------------------
extern "C" void kernel_launch(void* const* d_in, const int* in_sizes, int n_in,
                              void* d_out, int out_size) {
    (void)in_sizes; (void)n_in; (void)out_size;
    const float* x    = (const float*)d_in[0];
    const float* adj  = (const float*)d_in[1];
    const float* beta = (const float*)d_in[2];
    float* out = (float*)d_out;

    prep_kernel<<<BB * NN / 64, 256>>>(x, beta);

    cudaFuncSetAttribute(attn_mma, cudaFuncAttributeMaxDynamicSharedMemorySize, SMEM_TOTAL);
    dim3 grid(NN / TM, BB);
    attn_mma<<<grid, 128, SMEM_TOTAL>>>(x, adj, beta, out);
}